// round 13
// baseline (speedup 1.0000x reference)
#include <cuda_runtime.h>
#include <cuda_fp16.h>

// rate_RNN_mante: T=1000 sequential steps, B=64, IN=4, H=512, OUT=3.
// Wr = (l*pin) @ pout^T is rank-2 -> two H-wide reductions (s0,s1) per step.
//
// Scan: one CTA/batch, 4 warps x 32 lanes x 4 units. Loop = tanh chain,
// po-products, THREE shfl rounds (16 partials), STS float2, __syncthreads,
// 8x LDS.128 + packed f32x2 add tree (15 vec adds -> (s0,s1) in one reg).
// r exported as fp16 (2x cvt.f16x2 + STG.64) in the shuffle shadow.
// Project kernel reads fp16 r (65.5 MB) -> memory-bound ~17us.
// tanh = 1 - 2/(2^M+1), state pre-scaled by 2*log2(e) (EX2+RCP, ~1e-7 abs).

#define TSTEPS 1000
#define BATCH  64
#define HID    512
#define OUTDIM 3
#define NTHR   128
#define UPT    4
#define NROWS  (TSTEPS * BATCH)

// fp16 r scratch: [row][512 halves] as uint2 (4 halves each) -> 65.5 MB
__device__ uint2 g_rh[NROWS * (HID / 4)];

__device__ __forceinline__ unsigned long long add2(unsigned long long a,
                                                   unsigned long long b) {
    unsigned long long c;
    asm("add.rn.f32x2 %0, %1, %2;" : "=l"(c) : "l"(a), "l"(b));
    return c;
}

__global__ __launch_bounds__(NTHR, 1)
void rate_rnn_scan_kernel(const float* __restrict__ x,
                          const float* __restrict__ Win,
                          const float* __restrict__ pin,
                          const float* __restrict__ pout,
                          const float* __restrict__ l)
{
    const int b    = blockIdx.x;
    const int tid  = threadIdx.x;
    const int lane = tid & 31;
    const int wid  = tid >> 5;
    const int slot = wid * 4 + (lane >> 3);        // 16 partial slots
    const bool writer = ((lane & 7) == 0);

    __shared__ float4 xs[TSTEPS + 1];
    __shared__ __align__(16) float2 sp[2][16];     // double-buffered partials

    const float4* x4 = reinterpret_cast<const float4*>(x);  // x: [T,B,4,1]
    for (int t = tid; t < TSTEPS; t += NTHR)
        xs[t] = x4[t * BATCH + b];
    if (tid == 0) xs[TSTEPS] = make_float4(0.f, 0.f, 0.f, 0.f);

    const float lm = 0.90483741803595952735f;   // exp(-dt/taum) = exp(-0.1)
    const float cc = 2.88539008177792681472f;   // 2*log2(e); state M = cc*mem
    const float oc = (1.0f - lm) * cc;
    const float l0 = l[0], l1 = l[1];

    float4 wi[UPT];
    float  pi0[UPT], pi1[UPT], po0[UPT], po1[UPT];
    float  acc[UPT], M[UPT];
#pragma unroll
    for (int k = 0; k < UPT; ++k) {
        int h = tid * UPT + k;
        float4 w = reinterpret_cast<const float4*>(Win)[h];
        wi[k] = make_float4(w.x * oc, w.y * oc, w.z * oc, w.w * oc);
        pi0[k] = pin[h * 2 + 0] * l0 * oc;
        pi1[k] = pin[h * 2 + 1] * l1 * oc;
        po0[k] = pout[h * 2 + 0];
        po1[k] = pout[h * 2 + 1];
        M[k]   = 0.0f;
    }

    float s0 = 0.f, s1 = 0.f;
    int buf = 0;
    uint2* rrow = g_rh + (size_t)b * (HID / 4) + tid;

    __syncthreads();   // xs staged

    {   // prologue: acc for t=0 (M = 0)
        float4 x0 = xs[0];
#pragma unroll
        for (int k = 0; k < UPT; ++k)
            acc[k] = fmaf(wi[k].w, x0.w, fmaf(wi[k].z, x0.z,
                     fmaf(wi[k].y, x0.y, wi[k].x * x0.x)));
    }

    for (int t = 0; t < TSTEPS; ++t) {
        // ---- critical chain: s -> M -> tanh ----
        float r[UPT];
#pragma unroll
        for (int k = 0; k < UPT; ++k) {
            float m = fmaf(pi1[k], s1, fmaf(pi0[k], s0, acc[k]));
            M[k] = m;
            float e, rc;
            asm("ex2.approx.f32 %0, %1;" : "=f"(e)  : "f"(m));
            asm("rcp.approx.f32 %0, %1;" : "=f"(rc) : "f"(e + 1.0f));
            r[k] = fmaf(-2.0f, rc, 1.0f);
        }

        // s-products + THREE shfl rounds (16 partials across CTA)
        float v = fmaf(po0[1], r[1], po0[0] * r[0]) + fmaf(po0[3], r[3], po0[2] * r[2]);
        float u = fmaf(po1[1], r[1], po1[0] * r[0]) + fmaf(po1[3], r[3], po1[2] * r[2]);
#pragma unroll
        for (int off = 1; off <= 4; off <<= 1) {
            v += __shfl_down_sync(0xffffffffu, v, off);
            u += __shfl_down_sync(0xffffffffu, u, off);
        }

        // shuffle-shadow work: fp16 r export + next-step acc
        {
            __half2 h01 = __floats2half2_rn(r[0], r[1]);
            __half2 h23 = __floats2half2_rn(r[2], r[3]);
            union { __half2 h[2]; uint2 q; } pk;
            pk.h[0] = h01; pk.h[1] = h23;
            rrow[(size_t)t * (BATCH * (HID / 4))] = pk.q;
        }
        float4 xtn = xs[t + 1];
#pragma unroll
        for (int k = 0; k < UPT; ++k) {
            float iin = fmaf(wi[k].w, xtn.w, fmaf(wi[k].z, xtn.z,
                        fmaf(wi[k].y, xtn.y, wi[k].x * xtn.x)));
            acc[k] = fmaf(lm, M[k], iin);
        }

        if (writer) sp[buf][slot] = make_float2(v, u);
        __syncthreads();

        // 16 (v,u) partials: 8x LDS.128, packed f32x2 tree -> (s0,s1)
        const ulonglong2* q = reinterpret_cast<const ulonglong2*>(sp[buf]);
        ulonglong2 a0 = q[0], a1 = q[1], a2 = q[2], a3 = q[3];
        ulonglong2 a4 = q[4], a5 = q[5], a6 = q[6], a7 = q[7];
        unsigned long long b0 = add2(a0.x, a0.y), b1 = add2(a1.x, a1.y);
        unsigned long long b2 = add2(a2.x, a2.y), b3 = add2(a3.x, a3.y);
        unsigned long long b4 = add2(a4.x, a4.y), b5 = add2(a5.x, a5.y);
        unsigned long long b6 = add2(a6.x, a6.y), b7 = add2(a7.x, a7.y);
        unsigned long long c0 = add2(b0, b1), c1 = add2(b2, b3);
        unsigned long long c2 = add2(b4, b5), c3 = add2(b6, b7);
        unsigned long long e2 = add2(add2(c0, c1), add2(c2, c3));
        asm("mov.b64 {%0, %1}, %2;" : "=f"(s0), "=f"(s1) : "l"(e2));
        buf ^= 1;
    }
}

// y[row,o] = sum_h Wout[o,h]*r[row,h]; one warp per row, fp16 r.
__global__ __launch_bounds__(256, 4)
void project_y_kernel(const float* __restrict__ Wout, float* __restrict__ out)
{
    __shared__ __align__(16) float ws[OUTDIM * HID];   // 6 KB
    const int tid  = threadIdx.x;
    const int lane = tid & 31;
    const int wrp  = tid >> 5;

    for (int i = tid; i < OUTDIM * HID; i += 256)
        ws[i] = Wout[i];
    __syncthreads();

    int row = blockIdx.x * 8 + wrp;                    // [0, 64000)
    const uint4* rp = reinterpret_cast<const uint4*>(g_rh) + (size_t)row * (HID / 8);

    float y0 = 0.f, y1 = 0.f, y2 = 0.f;
#pragma unroll
    for (int j = 0; j < 2; ++j) {
        int m = lane * 2 + j;                          // uint4 idx: halves [8m,8m+8)
        uint4 wv = rp[m];
        int base = m * 8;
        const __half2* hp = reinterpret_cast<const __half2*>(&wv);
#pragma unroll
        for (int p = 0; p < 4; ++p) {
            float2 f = __half22float2(hp[p]);
            int h = base + 2 * p;
            y0 = fmaf(ws[h],            f.x, fmaf(ws[h + 1],            f.y, y0));
            y1 = fmaf(ws[HID + h],      f.x, fmaf(ws[HID + h + 1],      f.y, y1));
            y2 = fmaf(ws[2 * HID + h],  f.x, fmaf(ws[2 * HID + h + 1],  f.y, y2));
        }
    }
#pragma unroll
    for (int off = 16; off >= 1; off >>= 1) {
        y0 += __shfl_xor_sync(0xffffffffu, y0, off);
        y1 += __shfl_xor_sync(0xffffffffu, y1, off);
        y2 += __shfl_xor_sync(0xffffffffu, y2, off);
    }
    if (lane == 0) {
        out[row * OUTDIM + 0] = y0;   // y: [T,B,OUT,1], row = t*B + b
        out[row * OUTDIM + 1] = y1;
        out[row * OUTDIM + 2] = y2;
    }
}

extern "C" void kernel_launch(void* const* d_in, const int* in_sizes, int n_in,
                              void* d_out, int out_size)
{
    const float* x    = (const float*)d_in[0];  // [1000,64,4,1]
    const float* Win  = (const float*)d_in[1];  // [512,4]
    const float* Wout = (const float*)d_in[2];  // [3,512]
    const float* pin  = (const float*)d_in[3];  // [512,2]
    const float* pout = (const float*)d_in[4];  // [512,2]
    const float* l    = (const float*)d_in[5];  // [2]

    rate_rnn_scan_kernel<<<BATCH, NTHR>>>(x, Win, pin, pout, l);
    project_y_kernel<<<NROWS / 8, 256>>>(Wout, (float*)d_out);
}

// round 14
// speedup vs baseline: 1.3358x; 1.3358x over previous
#include <cuda_runtime.h>

// rate_RNN_mante: T=1000 sequential steps, B=64, IN=4, H=512, OUT=3.
// Wr = (l*pin) @ pout^T is rank-2 -> two H-wide reductions (s0,s1) per step.
//
// Scan (R11 structure): one CTA/batch, 4 warps x 32 lanes x 4 units. Loop =
// tanh chain, po-products, 4 shfl rounds, STS 8 partials, __syncthreads,
// 4 broadcast LDS.128 + scalar tree. r exported fp32 via STG.128 in the
// shuffle shadow. tanh via tanh.approx.f32 (MUFU.TANH): halves the per-step
// MUFU pipe floor (64->32 cyc/SMSP) and shortens the chain ~24 cyc.
// Project kernel (R11): y = Wout @ r, one warp per row, memory-bound.

#define TSTEPS 1000
#define BATCH  64
#define HID    512
#define OUTDIM 3
#define NTHR   128          // 4 warps
#define UPT    4            // hidden units per thread
#define NROWS  (TSTEPS * BATCH)

// r scratch: [T*B][128] float4  (131 MB)
__device__ float4 g_r[NROWS * (HID / 4)];

__global__ __launch_bounds__(NTHR, 1)
void rate_rnn_scan_kernel(const float* __restrict__ x,
                          const float* __restrict__ Win,
                          const float* __restrict__ pin,
                          const float* __restrict__ pout,
                          const float* __restrict__ l)
{
    const int b    = blockIdx.x;
    const int tid  = threadIdx.x;
    const int lane = tid & 31;
    const int wid  = tid >> 5;
    const int half = lane >> 4;            // 0: lanes 0-15, 1: lanes 16-31
    const int slot = wid * 2 + half;       // 8 partial slots
    const bool writer = ((lane & 15) == 0);

    __shared__ float4 xs[TSTEPS + 1];             // staged input (+1 pad)
    __shared__ __align__(16) float2 sp[2][8];     // double-buffered s partials

    const float4* x4 = reinterpret_cast<const float4*>(x);  // x: [T,B,4,1]
    for (int t = tid; t < TSTEPS; t += NTHR)
        xs[t] = x4[t * BATCH + b];
    if (tid == 0) xs[TSTEPS] = make_float4(0.f, 0.f, 0.f, 0.f);

    const float lm = 0.90483741803595952735f;   // exp(-dt/taum) = exp(-0.1)
    const float om = 1.0f - lm;                 // plain state (no ex2 prescale)
    const float l0 = l[0], l1 = l[1];

    float4 wi[UPT];
    float  pi0[UPT], pi1[UPT], po0[UPT], po1[UPT];
    float  acc[UPT], M[UPT];
#pragma unroll
    for (int k = 0; k < UPT; ++k) {
        int h = tid * UPT + k;
        float4 w = reinterpret_cast<const float4*>(Win)[h];
        wi[k] = make_float4(w.x * om, w.y * om, w.z * om, w.w * om);
        pi0[k] = pin[h * 2 + 0] * l0 * om;
        pi1[k] = pin[h * 2 + 1] * l1 * om;
        po0[k] = pout[h * 2 + 0];
        po1[k] = pout[h * 2 + 1];
        M[k]   = 0.0f;
    }

    float s0 = 0.f, s1 = 0.f;       // pout^T tanh(mem_{t-1}); zero at t=0
    int buf = 0;
    float4* rrow = g_r + (size_t)b * (HID / 4) + tid;

    __syncthreads();   // xs staged

    {   // prologue: acc for t=0 (M = 0)
        float4 x0 = xs[0];
#pragma unroll
        for (int k = 0; k < UPT; ++k)
            acc[k] = fmaf(wi[k].w, x0.w, fmaf(wi[k].z, x0.z,
                     fmaf(wi[k].y, x0.y, wi[k].x * x0.x)));
    }

    for (int t = 0; t < TSTEPS; ++t) {
        // ---- critical chain: s -> M -> tanh (single MUFU.TANH) ----
        float r[UPT];
#pragma unroll
        for (int k = 0; k < UPT; ++k) {
            float m = fmaf(pi1[k], s1, fmaf(pi0[k], s0, acc[k]));
            M[k] = m;
            asm("tanh.approx.f32 %0, %1;" : "=f"(r[k]) : "f"(m));
        }

        // s-products + 4 shuffle rounds (only pre-barrier reduction work)
        float v = fmaf(po0[1], r[1], po0[0] * r[0]) + fmaf(po0[3], r[3], po0[2] * r[2]);
        float u = fmaf(po1[1], r[1], po1[0] * r[0]) + fmaf(po1[3], r[3], po1[2] * r[2]);
#pragma unroll
        for (int off = 1; off <= 8; off <<= 1) {
            v += __shfl_down_sync(0xffffffffu, v, off);
            u += __shfl_down_sync(0xffffffffu, u, off);
        }

        // shuffle-shadow work: fp32 r export + next-step acc
        rrow[(size_t)t * (BATCH * (HID / 4))] = make_float4(r[0], r[1], r[2], r[3]);
        float4 xtn = xs[t + 1];
#pragma unroll
        for (int k = 0; k < UPT; ++k) {
            float iin = fmaf(wi[k].w, xtn.w, fmaf(wi[k].z, xtn.z,
                        fmaf(wi[k].y, xtn.y, wi[k].x * xtn.x)));
            acc[k] = fmaf(lm, M[k], iin);
        }

        if (writer) sp[buf][slot] = make_float2(v, u);
        __syncthreads();   // 4-warp barrier

        // 8 s-partials as 4 broadcast float4 loads + depth-3 tree
        const float4* q = reinterpret_cast<const float4*>(sp[buf]);
        float4 q0 = q[0], q1 = q[1], q2 = q[2], q3 = q[3];
        s0 = ((q0.x + q0.z) + (q1.x + q1.z)) + ((q2.x + q2.z) + (q3.x + q3.z));
        s1 = ((q0.y + q0.w) + (q1.y + q1.w)) + ((q2.y + q2.w) + (q3.y + q3.w));
        buf ^= 1;
    }
}

// y[row, o] = sum_h Wout[o,h] * r[row,h], row = t*BATCH + b. One warp per row.
__global__ __launch_bounds__(256, 4)
void project_y_kernel(const float* __restrict__ Wout, float* __restrict__ out)
{
    __shared__ __align__(16) float ws[OUTDIM * HID];   // 6 KB
    const int tid  = threadIdx.x;
    const int lane = tid & 31;
    const int wrp  = tid >> 5;

    for (int i = tid; i < OUTDIM * HID; i += 256)
        ws[i] = Wout[i];
    __syncthreads();

    const float4* ws4 = reinterpret_cast<const float4*>(ws);
    int row = blockIdx.x * 8 + wrp;                    // [0, 64000)
    const float4* rp = g_r + (size_t)row * (HID / 4);

    float y0 = 0.f, y1 = 0.f, y2 = 0.f;
#pragma unroll
    for (int j = 0; j < 4; ++j) {
        int idx = lane + 32 * j;                       // float4 index in row
        float4 rv = rp[idx];
        float4 a0 = ws4[0 * (HID / 4) + idx];
        float4 a1 = ws4[1 * (HID / 4) + idx];
        float4 a2 = ws4[2 * (HID / 4) + idx];
        y0 += fmaf(a0.w, rv.w, fmaf(a0.z, rv.z, fmaf(a0.y, rv.y, a0.x * rv.x)));
        y1 += fmaf(a1.w, rv.w, fmaf(a1.z, rv.z, fmaf(a1.y, rv.y, a1.x * rv.x)));
        y2 += fmaf(a2.w, rv.w, fmaf(a2.z, rv.z, fmaf(a2.y, rv.y, a2.x * rv.x)));
    }
#pragma unroll
    for (int off = 16; off >= 1; off >>= 1) {
        y0 += __shfl_xor_sync(0xffffffffu, y0, off);
        y1 += __shfl_xor_sync(0xffffffffu, y1, off);
        y2 += __shfl_xor_sync(0xffffffffu, y2, off);
    }
    if (lane == 0) {
        out[row * OUTDIM + 0] = y0;   // y: [T,B,OUT,1] -> row-major rows
        out[row * OUTDIM + 1] = y1;
        out[row * OUTDIM + 2] = y2;
    }
}

extern "C" void kernel_launch(void* const* d_in, const int* in_sizes, int n_in,
                              void* d_out, int out_size)
{
    const float* x    = (const float*)d_in[0];  // [1000,64,4,1]
    const float* Win  = (const float*)d_in[1];  // [512,4]
    const float* Wout = (const float*)d_in[2];  // [3,512]
    const float* pin  = (const float*)d_in[3];  // [512,2]
    const float* pout = (const float*)d_in[4];  // [512,2]
    const float* l    = (const float*)d_in[5];  // [2]

    rate_rnn_scan_kernel<<<BATCH, NTHR>>>(x, Win, pin, pout, l);
    project_y_kernel<<<NROWS / 8, 256>>>(Wout, (float*)d_out);
}